// round 1
// baseline (speedup 1.0000x reference)
#include <cuda_runtime.h>

#define NB 8
#define NTX 128
#define NTY 128
#define ND 512
#define NH 512
#define TYB 8

// Scratch (allocation-free rule: __device__ globals)
__device__ float g_WcT[NB * NH * NTX];   // [b][h][tx]
__device__ float g_UxT[NB * NH * NTY];   // [b][h][ty]

__device__ __forceinline__ float tanh_fast(float x) {
    float y;
    asm("tanh.approx.f32 %0, %1;" : "=f"(y) : "f"(x));
    return y;
}

// ---------------------------------------------------------------------------
// Kernel 1: OutT[b][h][t] = sum_d A[b][t][d] * W[d][h] + bias[h]
// A = context (which=0) or x (which=1). Output transposed for coalesced
// h-scan in kernel 2. Tiled 64(h) x 64(t), K-chunk 16, 4x4 per thread.
// ---------------------------------------------------------------------------
__global__ void __launch_bounds__(256)
bahdanau_gemm_t(const float* __restrict__ Ctx, const float* __restrict__ X,
                const float* __restrict__ Wa, const float* __restrict__ bWa,
                const float* __restrict__ Ua, const float* __restrict__ bUa)
{
    const int which = blockIdx.z >> 3;       // 0: Wc, 1: Ux
    const int b     = blockIdx.z & 7;
    const float* A    = (which ? X  : Ctx) + b * NTX * ND;   // [128][512]
    const float* W    =  which ? Ua : Wa;                    // [512][512]
    const float* bias =  which ? bUa : bWa;
    float* OutT = (which ? g_UxT : g_WcT) + b * NH * NTX;    // [512][128]

    __shared__ float As[16][64 + 4];  // [k][t]
    __shared__ float Bs[16][64 + 4];  // [k][h]

    const int h0 = blockIdx.x * 64;
    const int t0 = blockIdx.y * 64;
    const int tx = threadIdx.x;       // -> t
    const int ty = threadIdx.y;       // -> h
    const int tid = ty * 16 + tx;

    float acc[4][4];
#pragma unroll
    for (int j = 0; j < 4; j++)
#pragma unroll
        for (int i = 0; i < 4; i++) acc[j][i] = 0.f;

    for (int k0 = 0; k0 < ND; k0 += 16) {
        {   // A tile: 64 t x 16 k
            int t  = tid >> 2;
            int kl = (tid & 3) * 4;
            float4 v = *reinterpret_cast<const float4*>(&A[(t0 + t) * ND + k0 + kl]);
            As[kl + 0][t] = v.x; As[kl + 1][t] = v.y;
            As[kl + 2][t] = v.z; As[kl + 3][t] = v.w;
        }
        {   // W tile: 16 k x 64 h
            int r = tid >> 4;
            int c = (tid & 15) * 4;
            float4 v = *reinterpret_cast<const float4*>(&W[(k0 + r) * NH + h0 + c]);
            Bs[r][c + 0] = v.x; Bs[r][c + 1] = v.y;
            Bs[r][c + 2] = v.z; Bs[r][c + 3] = v.w;
        }
        __syncthreads();
#pragma unroll
        for (int kk = 0; kk < 16; kk++) {
            float a[4], w[4];
#pragma unroll
            for (int i = 0; i < 4; i++) a[i] = As[kk][tx * 4 + i];
#pragma unroll
            for (int j = 0; j < 4; j++) w[j] = Bs[kk][ty * 4 + j];
#pragma unroll
            for (int j = 0; j < 4; j++)
#pragma unroll
                for (int i = 0; i < 4; i++) acc[j][i] += w[j] * a[i];
        }
        __syncthreads();
    }

#pragma unroll
    for (int j = 0; j < 4; j++) {
        int h = h0 + ty * 4 + j;
        float bv = bias[h];
        float4 v = make_float4(acc[j][0] + bv, acc[j][1] + bv,
                               acc[j][2] + bv, acc[j][3] + bv);
        *reinterpret_cast<float4*>(&OutT[h * NTX + t0 + tx * 4]) = v;
    }
}

// ---------------------------------------------------------------------------
// Kernel 2: fused scores (tanh) + softmax + context-weighted sum + LayerNorm
// + residual. One block handles (b, 8 consecutive ty rows).
// 256 threads: (tx in [0,128), half in {0,1}); half splits the H range.
// ---------------------------------------------------------------------------
__global__ void __launch_bounds__(256)
bahdanau_attn(const float* __restrict__ Ctx, const float* __restrict__ X,
              const float* __restrict__ Va, const float* __restrict__ gamma,
              const float* __restrict__ beta, float* __restrict__ out)
{
    const int b   = blockIdx.x >> 4;
    const int ty0 = (blockIdx.x & 15) * TYB;

    __shared__ float ux_s[NH][TYB];        // 16 KB
    __shared__ float va_s[NH];             //  2 KB
    __shared__ float part[2][TYB][NTX];    //  8 KB
    __shared__ float attn_s[TYB][NTX];     //  4 KB
    __shared__ float cv_s[TYB][ND];        // 16 KB   (total 46 KB)

    const int tid = threadIdx.x;

    // Stage Ux rows (8 ty's, all h) and Va into shared
    for (int i = tid; i < NH * TYB; i += 256) {
        int h = i >> 3, j = i & 7;
        ux_s[h][j] = g_UxT[(b * NH + h) * NTY + ty0 + j];
    }
    for (int i = tid; i < NH; i += 256) va_s[i] = Va[i];
    __syncthreads();

    // ---- Phase 1: scores. s[j] = sum_h tanh(Wc[tx,h] + Ux[ty0+j,h]) * Va[h]
    const int txi  = tid & 127;
    const int half = tid >> 7;
    float s[TYB];
#pragma unroll
    for (int j = 0; j < TYB; j++) s[j] = 0.f;

    const float* wcp = g_WcT + (b * NH + half * 256) * NTX + txi;
#pragma unroll 4
    for (int hh = 0; hh < 256; hh++) {
        const int h = half * 256 + hh;
        const float w = __ldg(wcp + hh * NTX);
        const float v = va_s[h];
        float4 u0 = *reinterpret_cast<const float4*>(&ux_s[h][0]);
        float4 u1 = *reinterpret_cast<const float4*>(&ux_s[h][4]);
        s[0] += tanh_fast(w + u0.x) * v;
        s[1] += tanh_fast(w + u0.y) * v;
        s[2] += tanh_fast(w + u0.z) * v;
        s[3] += tanh_fast(w + u0.w) * v;
        s[4] += tanh_fast(w + u1.x) * v;
        s[5] += tanh_fast(w + u1.y) * v;
        s[6] += tanh_fast(w + u1.z) * v;
        s[7] += tanh_fast(w + u1.w) * v;
    }
#pragma unroll
    for (int j = 0; j < TYB; j++) part[half][j][txi] = s[j];
    __syncthreads();

    // ---- Phase 2: softmax over tx (128) per ty row; warp j handles row j.
    {
        const int w = tid >> 5, lane = tid & 31;
        const int j = w;  // 8 warps, 8 rows
        float vals[4];
        float mx = -1e30f;
#pragma unroll
        for (int i = 0; i < 4; i++) {
            int t = lane + i * 32;
            vals[i] = part[0][j][t] + part[1][j][t];
            mx = fmaxf(mx, vals[i]);
        }
#pragma unroll
        for (int off = 16; off; off >>= 1)
            mx = fmaxf(mx, __shfl_xor_sync(0xffffffffu, mx, off));
        float sum = 0.f;
#pragma unroll
        for (int i = 0; i < 4; i++) {
            vals[i] = __expf(vals[i] - mx);
            sum += vals[i];
        }
#pragma unroll
        for (int off = 16; off; off >>= 1)
            sum += __shfl_xor_sync(0xffffffffu, sum, off);
        float inv = __frcp_rn(sum);
#pragma unroll
        for (int i = 0; i < 4; i++)
            attn_s[j][lane + i * 32] = vals[i] * inv;
    }
    __syncthreads();

    // ---- Phase 3: cv[j][d] = sum_tx attn[j][tx] * context[b][tx][d]
    {
        const int d0 = tid * 2;  // each thread: 2 consecutive d
        float acc[TYB][2];
#pragma unroll
        for (int j = 0; j < TYB; j++) { acc[j][0] = 0.f; acc[j][1] = 0.f; }
        const float* cbase = Ctx + (size_t)b * NTX * ND + d0;
#pragma unroll 2
        for (int t = 0; t < NTX; t++) {
            float2 c = *reinterpret_cast<const float2*>(cbase + (size_t)t * ND);
#pragma unroll
            for (int j = 0; j < TYB; j++) {
                float a = attn_s[j][t];
                acc[j][0] += a * c.x;
                acc[j][1] += a * c.y;
            }
        }
#pragma unroll
        for (int j = 0; j < TYB; j++) {
            cv_s[j][d0]     = acc[j][0];
            cv_s[j][d0 + 1] = acc[j][1];
        }
    }
    __syncthreads();

    // ---- Phase 4: LayerNorm + residual. Warp j handles ty row j.
    {
        const int j = tid >> 5, lane = tid & 31;
        float vals[16];
        float sum = 0.f;
#pragma unroll
        for (int i = 0; i < 16; i++) {
            vals[i] = cv_s[j][i * 32 + lane];
            sum += vals[i];
        }
#pragma unroll
        for (int off = 16; off; off >>= 1)
            sum += __shfl_xor_sync(0xffffffffu, sum, off);
        const float mean = sum * (1.0f / ND);
        float vsum = 0.f;
#pragma unroll
        for (int i = 0; i < 16; i++) {
            float dlt = vals[i] - mean;
            vsum += dlt * dlt;
        }
#pragma unroll
        for (int off = 16; off; off >>= 1)
            vsum += __shfl_xor_sync(0xffffffffu, vsum, off);
        const float scale = rsqrtf(vsum * (1.0f / ND) + 1e-3f);

        const int ty = ty0 + j;
        const float* xr = X + ((size_t)b * NTY + ty) * ND;
        float* orow = out + ((size_t)b * NTY + ty) * ND;
#pragma unroll
        for (int i = 0; i < 16; i++) {
            int d = i * 32 + lane;
            orow[d] = (vals[i] - mean) * scale * gamma[d] + beta[d] + xr[d];
        }
    }
}

// ---------------------------------------------------------------------------
extern "C" void kernel_launch(void* const* d_in, const int* in_sizes, int n_in,
                              void* d_out, int out_size)
{
    const float* ctx   = (const float*)d_in[0];
    const float* x     = (const float*)d_in[1];
    const float* Wa    = (const float*)d_in[2];
    const float* bWa   = (const float*)d_in[3];
    const float* Ua    = (const float*)d_in[4];
    const float* bUa   = (const float*)d_in[5];
    const float* Va    = (const float*)d_in[6];
    // d_in[7] = bVa: scalar added to scores; cancels exactly in softmax.
    const float* gamma = (const float*)d_in[8];
    const float* beta  = (const float*)d_in[9];
    float* out = (float*)d_out;

    dim3 g1(NH / 64, NTX / 64, NB * 2);   // (8, 2, 16)
    dim3 b1(16, 16);
    bahdanau_gemm_t<<<g1, b1>>>(ctx, x, Wa, bWa, Ua, bUa);

    bahdanau_attn<<<NB * (NTY / TYB), 256>>>(ctx, x, Va, gamma, beta, out);
}

// round 2
// speedup vs baseline: 1.2708x; 1.2708x over previous
#include <cuda_runtime.h>

#define NB 8
#define NTX 128
#define NTY 128
#define ND 512
#define NH 512
#define TYB 8

// Scratch (allocation-free rule: __device__ globals)
__device__ float g_WcT[NB * NH * NTX];   // [b][h][tx]
__device__ float g_UxT[NB * NH * NTY];   // [b][h][ty]

__device__ __forceinline__ float tanh_fast(float x) {
    float y;
    asm("tanh.approx.f32 %0, %1;" : "=f"(y) : "f"(x));
    return y;
}

// ---------------------------------------------------------------------------
// Kernel 1: OutT[b][h][t] = sum_d A[b][t][d] * W[d][h] + bias[h]
// (unchanged from R1)
// ---------------------------------------------------------------------------
__global__ void __launch_bounds__(256)
bahdanau_gemm_t(const float* __restrict__ Ctx, const float* __restrict__ X,
                const float* __restrict__ Wa, const float* __restrict__ bWa,
                const float* __restrict__ Ua, const float* __restrict__ bUa)
{
    const int which = blockIdx.z >> 3;       // 0: Wc, 1: Ux
    const int b     = blockIdx.z & 7;
    const float* A    = (which ? X  : Ctx) + b * NTX * ND;   // [128][512]
    const float* W    =  which ? Ua : Wa;                    // [512][512]
    const float* bias =  which ? bUa : bWa;
    float* OutT = (which ? g_UxT : g_WcT) + b * NH * NTX;    // [512][128]

    __shared__ float As[16][64 + 4];  // [k][t]
    __shared__ float Bs[16][64 + 4];  // [k][h]

    const int h0 = blockIdx.x * 64;
    const int t0 = blockIdx.y * 64;
    const int tx = threadIdx.x;       // -> t
    const int ty = threadIdx.y;       // -> h
    const int tid = ty * 16 + tx;

    float acc[4][4];
#pragma unroll
    for (int j = 0; j < 4; j++)
#pragma unroll
        for (int i = 0; i < 4; i++) acc[j][i] = 0.f;

    for (int k0 = 0; k0 < ND; k0 += 16) {
        {   // A tile: 64 t x 16 k
            int t  = tid >> 2;
            int kl = (tid & 3) * 4;
            float4 v = *reinterpret_cast<const float4*>(&A[(t0 + t) * ND + k0 + kl]);
            As[kl + 0][t] = v.x; As[kl + 1][t] = v.y;
            As[kl + 2][t] = v.z; As[kl + 3][t] = v.w;
        }
        {   // W tile: 16 k x 64 h
            int r = tid >> 4;
            int c = (tid & 15) * 4;
            float4 v = *reinterpret_cast<const float4*>(&W[(k0 + r) * NH + h0 + c]);
            Bs[r][c + 0] = v.x; Bs[r][c + 1] = v.y;
            Bs[r][c + 2] = v.z; Bs[r][c + 3] = v.w;
        }
        __syncthreads();
#pragma unroll
        for (int kk = 0; kk < 16; kk++) {
            float a[4], w[4];
#pragma unroll
            for (int i = 0; i < 4; i++) a[i] = As[kk][tx * 4 + i];
#pragma unroll
            for (int j = 0; j < 4; j++) w[j] = Bs[kk][ty * 4 + j];
#pragma unroll
            for (int j = 0; j < 4; j++)
#pragma unroll
                for (int i = 0; i < 4; i++) acc[j][i] += w[j] * a[i];
        }
        __syncthreads();
    }

#pragma unroll
    for (int j = 0; j < 4; j++) {
        int h = h0 + ty * 4 + j;
        float bv = bias[h];
        float4 v = make_float4(acc[j][0] + bv, acc[j][1] + bv,
                               acc[j][2] + bv, acc[j][3] + bv);
        *reinterpret_cast<float4*>(&OutT[h * NTX + t0 + tx * 4]) = v;
    }
}

// ---------------------------------------------------------------------------
// Kernel 2: fused scores (tanh) + softmax + context-weighted sum + LayerNorm
// + residual. One block handles (b, 8 consecutive ty rows). 512 threads:
// phase 1 splits H 4-way (4 x 128 tx-threads), depth-4 prefetch of WcT.
//
// Shared pool overlay:
//   phase 0-2:  pool[0..4096)    = ux_s[h][j]           (16 KB)
//               pool[4096..8192) = part[q][j][txi]      (16 KB)
//   phase 3-4:  pool[0..8192)    = cvp[g][j][d]         (32 KB)
// ---------------------------------------------------------------------------
__global__ void __launch_bounds__(512)
bahdanau_attn(const float* __restrict__ Ctx, const float* __restrict__ X,
              const float* __restrict__ Va, const float* __restrict__ gamma,
              const float* __restrict__ beta, float* __restrict__ out)
{
    const int b   = blockIdx.x >> 4;
    const int ty0 = (blockIdx.x & 15) * TYB;

    __shared__ __align__(16) float va_s[NH];        //  2 KB
    __shared__ __align__(16) float pool[8192];      // 32 KB (overlaid)
    __shared__ __align__(16) float attn_s[TYB][NTX];//  4 KB

    const int tid = threadIdx.x;

    // Stage Ux rows (8 ty's, all h) and Va into shared
    for (int i = tid; i < NH * TYB; i += 512) {
        int h = i >> 3, j = i & 7;
        pool[i] = g_UxT[(b * NH + h) * NTY + ty0 + j];  // ux_s[h][j]
    }
    if (tid < NH) va_s[tid] = Va[tid];
    __syncthreads();

    // ---- Phase 1: s[j] = sum_h tanh(Wc[tx,h] + Ux[ty0+j,h]) * Va[h]
    // quarter q handles h in [q*128, q*128+128)
    {
        const int txi = tid & 127;
        const int q   = tid >> 7;
        float s[TYB];
#pragma unroll
        for (int j = 0; j < TYB; j++) s[j] = 0.f;

        const float* wp = g_WcT + (b * NH + q * 128) * NTX + txi;

        float wr[4];
#pragma unroll
        for (int i = 0; i < 4; i++) wr[i] = __ldg(wp + i * NTX);

#pragma unroll 1
        for (int hh = 0; hh < 128; hh += 4) {
            float wn[4];
            const bool more = (hh + 4) < 128;
#pragma unroll
            for (int i = 0; i < 4; i++)
                wn[i] = more ? __ldg(wp + (hh + 4 + i) * NTX) : 0.f;

#pragma unroll
            for (int i = 0; i < 4; i++) {
                const int h = q * 128 + hh + i;
                const float v = va_s[h];
                const float w = wr[i];
                float4 u0 = *reinterpret_cast<const float4*>(&pool[h * 8]);
                float4 u1 = *reinterpret_cast<const float4*>(&pool[h * 8 + 4]);
                s[0] += tanh_fast(w + u0.x) * v;
                s[1] += tanh_fast(w + u0.y) * v;
                s[2] += tanh_fast(w + u0.z) * v;
                s[3] += tanh_fast(w + u0.w) * v;
                s[4] += tanh_fast(w + u1.x) * v;
                s[5] += tanh_fast(w + u1.y) * v;
                s[6] += tanh_fast(w + u1.z) * v;
                s[7] += tanh_fast(w + u1.w) * v;
            }
#pragma unroll
            for (int i = 0; i < 4; i++) wr[i] = wn[i];
        }
        __syncthreads();   // ux_s reads done before part writes? (disjoint, but keep order)
#pragma unroll
        for (int j = 0; j < TYB; j++)
            pool[4096 + q * 1024 + j * 128 + txi] = s[j];
    }
    __syncthreads();

    // ---- Phase 2: softmax over tx (128) per ty row; warp j (j<8) handles row j.
    if (tid < 256) {
        const int j = tid >> 5, lane = tid & 31;
        float vals[4];
        float mx = -1e30f;
#pragma unroll
        for (int i = 0; i < 4; i++) {
            int t = lane + i * 32;
            vals[i] = pool[4096 + 0 * 1024 + j * 128 + t]
                    + pool[4096 + 1 * 1024 + j * 128 + t]
                    + pool[4096 + 2 * 1024 + j * 128 + t]
                    + pool[4096 + 3 * 1024 + j * 128 + t];
            mx = fmaxf(mx, vals[i]);
        }
#pragma unroll
        for (int off = 16; off; off >>= 1)
            mx = fmaxf(mx, __shfl_xor_sync(0xffffffffu, mx, off));
        float sum = 0.f;
#pragma unroll
        for (int i = 0; i < 4; i++) {
            vals[i] = __expf(vals[i] - mx);
            sum += vals[i];
        }
#pragma unroll
        for (int off = 16; off; off >>= 1)
            sum += __shfl_xor_sync(0xffffffffu, sum, off);
        float inv = __frcp_rn(sum);
#pragma unroll
        for (int i = 0; i < 4; i++)
            attn_s[j][lane + i * 32] = vals[i] * inv;
    }
    __syncthreads();

    // ---- Phase 3: cv[j][d] = sum_tx attn[j][tx] * context[b][tx][d]
    // group g (0/1) covers t in [g*64, g*64+64); each thread: 2 consecutive d.
    {
        const int g  = tid >> 8;
        const int l  = tid & 255;
        const int d0 = l * 2;
        float acc[TYB][2];
#pragma unroll
        for (int j = 0; j < TYB; j++) { acc[j][0] = 0.f; acc[j][1] = 0.f; }
        const float* cbase = Ctx + (size_t)b * NTX * ND + (size_t)(g * 64) * ND + d0;
#pragma unroll 4
        for (int t = 0; t < 64; t++) {
            float2 c = *reinterpret_cast<const float2*>(cbase + (size_t)t * ND);
            const int tt = g * 64 + t;
#pragma unroll
            for (int j = 0; j < TYB; j++) {
                float a = attn_s[j][tt];
                acc[j][0] += a * c.x;
                acc[j][1] += a * c.y;
            }
        }
#pragma unroll
        for (int j = 0; j < TYB; j++) {
            pool[g * 4096 + j * 512 + d0]     = acc[j][0];  // cvp[g][j][d]
            pool[g * 4096 + j * 512 + d0 + 1] = acc[j][1];
        }
    }
    __syncthreads();

    // ---- Phase 4: LayerNorm + residual. Warp j (j<8) handles ty row j.
    if (tid < 256) {
        const int j = tid >> 5, lane = tid & 31;
        float vals[16];
        float sum = 0.f;
#pragma unroll
        for (int i = 0; i < 16; i++) {
            int d = i * 32 + lane;
            vals[i] = pool[j * 512 + d] + pool[4096 + j * 512 + d];
            sum += vals[i];
        }
#pragma unroll
        for (int off = 16; off; off >>= 1)
            sum += __shfl_xor_sync(0xffffffffu, sum, off);
        const float mean = sum * (1.0f / ND);
        float vsum = 0.f;
#pragma unroll
        for (int i = 0; i < 16; i++) {
            float dlt = vals[i] - mean;
            vsum += dlt * dlt;
        }
#pragma unroll
        for (int off = 16; off; off >>= 1)
            vsum += __shfl_xor_sync(0xffffffffu, vsum, off);
        const float scale = rsqrtf(vsum * (1.0f / ND) + 1e-3f);

        const int ty = ty0 + j;
        const float* xr = X + ((size_t)b * NTY + ty) * ND;
        float* orow = out + ((size_t)b * NTY + ty) * ND;
#pragma unroll
        for (int i = 0; i < 16; i++) {
            int d = i * 32 + lane;
            orow[d] = (vals[i] - mean) * scale * gamma[d] + beta[d] + xr[d];
        }
    }
}

// ---------------------------------------------------------------------------
extern "C" void kernel_launch(void* const* d_in, const int* in_sizes, int n_in,
                              void* d_out, int out_size)
{
    const float* ctx   = (const float*)d_in[0];
    const float* x     = (const float*)d_in[1];
    const float* Wa    = (const float*)d_in[2];
    const float* bWa   = (const float*)d_in[3];
    const float* Ua    = (const float*)d_in[4];
    const float* bUa   = (const float*)d_in[5];
    const float* Va    = (const float*)d_in[6];
    // d_in[7] = bVa: scalar added to scores; cancels exactly in softmax.
    const float* gamma = (const float*)d_in[8];
    const float* beta  = (const float*)d_in[9];
    float* out = (float*)d_out;

    dim3 g1(NH / 64, NTX / 64, NB * 2);   // (8, 2, 16)
    dim3 b1(16, 16);
    bahdanau_gemm_t<<<g1, b1>>>(ctx, x, Wa, bWa, Ua, bUa);

    bahdanau_attn<<<NB * (NTY / TYB), 512>>>(ctx, x, Va, gamma, beta, out);
}